// round 14
// baseline (speedup 1.0000x reference)
#include <cuda_runtime.h>
#include <cstdint>

#define NQ 65536
#define NC 2048
#define ASM 132   // activation smem row stride (floats), 132 % 32 == 4
#define WSM 136   // weight-tile smem row stride (floats), 136 % 32 == 8

// ------- device scratch (static __device__ globals: allocation-free) -------
__device__ float g_X[NQ * 128];    // tf32-rounded [query_codes 64 | xyz 63 | 0]
__device__ float g_V[NQ * 64];     // dir @ Wd_dir + bd  (fp32)
__device__ int   g_hist[4096];
__device__ int   g_offs[4096];
__device__ int   g_perm[NQ];
__device__ float4 g_cps[NC];       // code positions sorted by cell: {x,y,z,|c|^2}
__device__ int    g_cmap[NC];      // sorted index -> original code index
__device__ float g_W0p[128 * 128]; // all weights tf32-rounded, padded
__device__ float g_W1p[128 * 128];
__device__ float g_W2xp[128 * 128];
__device__ float g_W2hp[128 * 128];
__device__ float g_W3p[128 * 128];
__device__ float g_Wfp[128 * 128];
__device__ float g_Wdfp[128 * 64];

// ------------------------- helpers -----------------------------------------
__device__ __forceinline__ float to_tf32(float x) {
    float r; asm("cvt.rna.tf32.f32 %0, %1;" : "=f"(r) : "f"(x)); return r;
}
__device__ __forceinline__ void mma8(float* c, const float* a, float b0, float b1) {
    asm volatile(
        "mma.sync.aligned.m16n8k8.row.col.f32.tf32.tf32.f32 "
        "{%0,%1,%2,%3}, {%4,%5,%6,%7}, {%8,%9}, {%0,%1,%2,%3};"
        : "+f"(c[0]), "+f"(c[1]), "+f"(c[2]), "+f"(c[3])
        : "r"(__float_as_uint(a[0])), "r"(__float_as_uint(a[1])),
          "r"(__float_as_uint(a[2])), "r"(__float_as_uint(a[3])),
          "r"(__float_as_uint(b0)), "r"(__float_as_uint(b1)));
}
__device__ __forceinline__ int cell_of(float x, float y, float z) {
    int ix = min(15, max(0, (int)(x * 16.f)));
    int iy = min(15, max(0, (int)(y * 16.f)));
    int iz = min(15, max(0, (int)(z * 16.f)));
    return (ix << 8) | (iy << 4) | iz;
}

// --------------------- spatial counting sort of queries --------------------
__global__ void hist_k(const float* __restrict__ qp) {
    int q = blockIdx.x * 256 + threadIdx.x;
    atomicAdd(&g_hist[cell_of(qp[3 * q], qp[3 * q + 1], qp[3 * q + 2])], 1);
}

__global__ void __launch_bounds__(1024) scan_k() {   // 1 block
    __shared__ int s[1024];
    int tid = threadIdx.x;
    int v[4]; int sum = 0;
#pragma unroll
    for (int i = 0; i < 4; i++) { v[i] = g_hist[tid * 4 + i]; sum += v[i]; }
    s[tid] = sum; __syncthreads();
    for (int off = 1; off < 1024; off <<= 1) {
        int t = (tid >= off) ? s[tid - off] : 0;
        __syncthreads();
        s[tid] += t;
        __syncthreads();
    }
    int run = tid ? s[tid - 1] : 0;
#pragma unroll
    for (int i = 0; i < 4; i++) { g_offs[tid * 4 + i] = run; run += v[i]; }
}

__global__ void scatter_k(const float* __restrict__ qp) {
    int q = blockIdx.x * 256 + threadIdx.x;
    int cell = cell_of(qp[3 * q], qp[3 * q + 1], qp[3 * q + 2]);
    int pos = atomicAdd(&g_offs[cell], 1);
    g_perm[pos] = q;
}

// ------- sort code positions by cell (deterministic bitonic, 1 block) ------
__global__ void __launch_bounds__(256) sort_codes(const int* __restrict__ indices,
                                                  const float* __restrict__ cpos) {
    __shared__ unsigned key[NC];   // (cell << 11) | original index
    int tid = threadIdx.x;
    int ib = indices[0];
    const float* cp = cpos + (size_t)ib * NC * 3;
    for (int i = tid; i < NC; i += 256) {
        int cell = cell_of(cp[3 * i], cp[3 * i + 1], cp[3 * i + 2]);
        key[i] = ((unsigned)cell << 11) | (unsigned)i;
    }
    __syncthreads();
    for (int k = 2; k <= NC; k <<= 1) {
        for (int j = k >> 1; j > 0; j >>= 1) {
            for (int t = tid; t < NC; t += 256) {
                int p = t ^ j;
                if (p > t) {
                    bool up = ((t & k) == 0);
                    unsigned a = key[t], b = key[p];
                    if ((a > b) == up) { key[t] = b; key[p] = a; }
                }
            }
            __syncthreads();
        }
    }
    for (int i = tid; i < NC; i += 256) {
        int c = key[i] & 0x7FF;
        float x = cp[3 * c], y = cp[3 * c + 1], z = cp[3 * c + 2];
        g_cps[i] = make_float4(x, y, z, fmaf(x, x, fmaf(y, y, z * z)));
        g_cmap[i] = c;
    }
}

// ------ merged prologue: weight prep (tf32) | xyz pack | V comp ------------
__global__ void __launch_bounds__(256) prologue_k(
        const float* __restrict__ W0, const float* __restrict__ W1,
        const float* __restrict__ W2, const float* __restrict__ W3,
        const float* __restrict__ Wf, const float* __restrict__ Wd,
        const float* __restrict__ bd, const float* __restrict__ xyzdir) {
    int bid = blockIdx.x;
    int tid = threadIdx.x;
    const int T = 16384;
    if (bid < 224) {
        int total = 6 * T + 8192;
        for (int i = bid * 256 + tid; i < total; i += 224 * 256) {
            if (i < T) {
                int r = i >> 7, c = i & 127;
                g_W0p[i] = (r < 127) ? to_tf32(W0[r * 128 + c]) : 0.f;
            } else if (i < 2 * T) {
                int j = i - T;
                g_W1p[j] = to_tf32(W1[j]);
            } else if (i < 3 * T) {
                int j = i - 2 * T; int r = j >> 7, c = j & 127;
                g_W2xp[j] = (r < 127) ? to_tf32(W2[r * 128 + c]) : 0.f;
            } else if (i < 4 * T) {
                int j = i - 3 * T; int r = j >> 7, c = j & 127;
                g_W2hp[j] = to_tf32(W2[(127 + r) * 128 + c]);
            } else if (i < 5 * T) {
                int j = i - 4 * T;
                g_W3p[j] = to_tf32(W3[j]);
            } else if (i < 6 * T) {
                int j = i - 5 * T;
                g_Wfp[j] = to_tf32(Wf[j]);
            } else {
                int j = i - 6 * T;
                g_Wdfp[j] = to_tf32(Wd[j]);
            }
        }
    } else if (bid < 1248) {
        const int total = NQ * 64;
        for (int i = (bid - 224) * 256 + tid; i < total; i += 1024 * 256) {
            int q = i >> 6, e = i & 63;
            g_X[q * 128 + 64 + e] = (e < 63) ? to_tf32(xyzdir[q * 90 + e]) : 0.f;
        }
    } else {
        __shared__ float sw[27 * 64];
        __shared__ float sb[64];
        for (int i = tid; i < 27 * 64; i += 256) sw[i] = Wd[128 * 64 + i];
        if (tid < 64) sb[tid] = bd[tid];
        __syncthreads();
        int idx = (bid - 1248) * 256 + tid;     // NQ*16 threads
        int q = idx >> 4, c0 = (idx & 15) * 4;
        float a0 = sb[c0], a1 = sb[c0 + 1], a2 = sb[c0 + 2], a3 = sb[c0 + 3];
        const float* dirp = xyzdir + (size_t)q * 90 + 63;
#pragma unroll
        for (int k = 0; k < 27; k++) {
            float dv = dirp[k];
            a0 = fmaf(dv, sw[k * 64 + c0 + 0], a0);
            a1 = fmaf(dv, sw[k * 64 + c0 + 1], a1);
            a2 = fmaf(dv, sw[k * 64 + c0 + 2], a2);
            a3 = fmaf(dv, sw[k * 64 + c0 + 3], a3);
        }
        *reinterpret_cast<float4*>(g_V + (size_t)q * 64 + c0) =
            make_float4(a0, a1, a2, a3);
    }
}

// --------- KNN(16) + interpolation; warm-start scan over sorted codes ------
__global__ void __launch_bounds__(128) knn_interp(const int* __restrict__ indices,
                                                  const float* __restrict__ qp,
                                                  const float* __restrict__ codes) {
    __shared__ float4 sp[NC];      // sorted {x, y, z, ||c||^2}
    __shared__ float s_w[128 * 16];
    __shared__ int   s_i[128 * 16];
    int tid = threadIdx.x;
    int ib = indices[0];
    const float* cc = codes + (size_t)ib * NC * 64;
    for (int c = tid; c < NC; c += 128) sp[c] = g_cps[c];
    __syncthreads();

    int q = g_perm[blockIdx.x * 128 + tid];
    float qx = qp[q * 3 + 0], qy = qp[q * 3 + 1], qz = qp[q * 3 + 2];
    float qx2 = -2.f * qx, qy2 = -2.f * qy, qz2 = -2.f * qz;
    float q2 = fmaf(qx, qx, fmaf(qy, qy, qz * qz));

    unsigned bk[16];
#pragma unroll
    for (int j = 0; j < 16; j++) bk[j] = 0x7F7FFFFFu;
    float bnd = __uint_as_float(0x7F7FF800u) - q2;

    // warm start: queries and codes sorted by the SAME cell raster order, so
    // block b's queries are near sorted candidates around rank b*NC/512.
    int start = blockIdx.x * (NC / 512);      // 4-aligned, warp-uniform

#define KNN_GROUP(c)  do {                                                   \
        float dp[4];                                                         \
        _Pragma("unroll")                                                    \
        for (int i = 0; i < 4; i++) {                                        \
            float4 v = sp[(c) + i];                                          \
            dp[i] = fmaf(v.x, qx2, fmaf(v.y, qy2, fmaf(v.z, qz2, v.w)));     \
        }                                                                    \
        float mn4 = fminf(fminf(dp[0], dp[1]), fminf(dp[2], dp[3]));         \
        if (mn4 < bnd) {                                                     \
            _Pragma("unroll")                                                \
            for (int i = 0; i < 4; i++) {                                    \
                if (dp[i] < bnd) {                                           \
                    float dfull = fmaxf(dp[i] + q2, 0.f);                    \
                    unsigned cur = (__float_as_uint(dfull) & 0xFFFFF800u)    \
                                 | (unsigned)((c) + i);                      \
                    _Pragma("unroll")                                        \
                    for (int j = 0; j < 16; j++) {                           \
                        unsigned lo = min(bk[j], cur);                       \
                        unsigned hi = max(bk[j], cur);                       \
                        bk[j] = lo; cur = hi;                                \
                    }                                                        \
                    bnd = __uint_as_float(bk[15] & 0xFFFFF800u) - q2;        \
                }                                                            \
            }                                                                \
        }                                                                    \
    } while (0)

    for (int c = start; c < NC; c += 4) KNN_GROUP(c);
    for (int c = 0; c < start; c += 4) KNN_GROUP(c);
#undef KNN_GROUP

    // exact distances -> normalized 1/d2 weights; remap to original indices
    float w[16]; int ci[16]; float wsum = 0.f;
#pragma unroll
    for (int k = 0; k < 16; k++) {
        int cs = (int)(bk[k] & 0x7FFu);
        ci[k] = g_cmap[cs];
        float4 v = sp[cs];
        float dx = qx - v.x, dy = qy - v.y, dz = qz - v.z;
        float d2 = fmaf(dx, dx, fmaf(dy, dy, dz * dz)) + 1e-16f;
        w[k] = 1.0f / d2; wsum += w[k];
    }
    float inv = 1.0f / wsum;
#pragma unroll
    for (int k = 0; k < 16; k++) {
        s_w[tid * 16 + k] = w[k] * inv;
        s_i[tid * 16 + k] = ci[k];
    }
    __syncwarp();

    int lane = tid & 31;
    int wbase2 = tid & ~31;
    for (int s = 0; s < 32; s++) {
        int t = wbase2 + s;
        int qq = __shfl_sync(0xFFFFFFFFu, q, s);
        float a0 = 0.f, a1 = 0.f;
#pragma unroll
        for (int k = 0; k < 16; k++) {
            int cix = s_i[t * 16 + k];
            float wk = s_w[t * 16 + k];
            const float* row = cc + cix * 64;
            a0 = fmaf(wk, row[lane], a0);
            a1 = fmaf(wk, row[lane + 32], a1);
        }
        g_X[(size_t)qq * 128 + lane] = to_tf32(a0);
        g_X[(size_t)qq * 128 + 32 + lane] = to_tf32(a1);
    }
}

// ===================== fused MLP: tf32 mma.sync ============================
#define SMEM_FLOATS (128 * ASM + 2 * 32 * WSM + 128 + 192)

__device__ __forceinline__ void mma_tile(float acc[2][8][4], const float* A,
        const float* Wt, int abase, int w_r, int w_c, int g, int t) {
#pragma unroll
    for (int k8 = 0; k8 < 4; k8++) {
        int ak = abase + k8 * 8;
        int r0 = w_r * 32 + g;
        float a0[4], a1[4];
        a0[0] = A[r0 * ASM + ak + t];
        a0[1] = A[(r0 + 8) * ASM + ak + t];
        a0[2] = A[r0 * ASM + ak + t + 4];
        a0[3] = A[(r0 + 8) * ASM + ak + t + 4];
        a1[0] = A[(r0 + 16) * ASM + ak + t];
        a1[1] = A[(r0 + 24) * ASM + ak + t];
        a1[2] = A[(r0 + 16) * ASM + ak + t + 4];
        a1[3] = A[(r0 + 24) * ASM + ak + t + 4];
        int kw = k8 * 8;
#pragma unroll
        for (int j = 0; j < 8; j++) {
            int cb = w_c * 64 + j * 8 + g;
            float b0 = Wt[(kw + t) * WSM + cb];
            float b1 = Wt[(kw + t + 4) * WSM + cb];
            mma8(acc[0][j], a0, b0, b1);
            mma8(acc[1][j], a1, b0, b1);
        }
    }
}

__device__ __forceinline__ void run128_db(const float* __restrict__ Wg,
        float acc[2][8][4], const float* A, float* Wb,
        int tid, int w_r, int w_c, int g, int t) {
    int sc4 = (tid & 31) * 4;
    int sk  = (tid >> 5) * 4;
    float4 pf[4];
#pragma unroll
    for (int i = 0; i < 4; i++)
        pf[i] = *reinterpret_cast<const float4*>(Wg + (size_t)(sk + i) * 128 + sc4);
#pragma unroll
    for (int i = 0; i < 4; i++)
        *reinterpret_cast<float4*>(Wb + (sk + i) * WSM + sc4) = pf[i];
    __syncthreads();
    for (int tt = 0; tt < 4; tt++) {
        if (tt < 3) {
#pragma unroll
            for (int i = 0; i < 4; i++)
                pf[i] = *reinterpret_cast<const float4*>(
                    Wg + (size_t)((tt + 1) * 32 + sk + i) * 128 + sc4);
        }
        mma_tile(acc, A, Wb + (tt & 1) * (32 * WSM), tt * 32, w_r, w_c, g, t);
        if (tt < 3) {
            float* d = Wb + ((tt + 1) & 1) * (32 * WSM);
#pragma unroll
            for (int i = 0; i < 4; i++)
                *reinterpret_cast<float4*>(d + (sk + i) * WSM + sc4) = pf[i];
        }
        __syncthreads();
    }
}

__device__ __forceinline__ void run128_sx(const float* __restrict__ Wg,
        float acc[2][8][4], float* A, float* Wb,
        int tid, int w_r, int w_c, int g, int t,
        const float* __restrict__ xsrc) {
    int sc4 = (tid & 31) * 4;
    int sk  = (tid >> 5) * 4;
    for (int tt = 0; tt < 4; tt++) {
        __syncthreads();
#pragma unroll
        for (int i = 0; i < 4; i++) {
            float4 v = *reinterpret_cast<const float4*>(
                Wg + (size_t)(tt * 32 + sk + i) * 128 + sc4);
            *reinterpret_cast<float4*>(Wb + (sk + i) * WSM + sc4) = v;
        }
#pragma unroll
        for (int i = 0; i < 4; i++) {
            int row = (tid >> 3) + i * 32;
            int c4 = (tid & 7) * 4;
            float4 v = *reinterpret_cast<const float4*>(
                xsrc + (size_t)row * 128 + tt * 32 + c4);
            *reinterpret_cast<float4*>(A + row * ASM + c4) = v;
        }
        __syncthreads();
        mma_tile(acc, A, Wb, 0, w_r, w_c, g, t);
    }
    __syncthreads();
}

__device__ __forceinline__ void ep128(float acc[2][8][4],
        const float* __restrict__ bias, bool relu,
        float* A, int w_r, int w_c, int g, int t) {
    __syncthreads();
#pragma unroll
    for (int m = 0; m < 2; m++) {
        int r0 = w_r * 32 + m * 16 + g;
#pragma unroll
        for (int j = 0; j < 8; j++) {
            int C = w_c * 64 + j * 8 + 2 * t;
            float bv0 = bias[C], bv1 = bias[C + 1];
            float v0 = acc[m][j][0] + bv0, v1 = acc[m][j][1] + bv1;
            float v2 = acc[m][j][2] + bv0, v3 = acc[m][j][3] + bv1;
            if (relu) {
                v0 = fmaxf(v0, 0.f); v1 = fmaxf(v1, 0.f);
                v2 = fmaxf(v2, 0.f); v3 = fmaxf(v3, 0.f);
            }
            v0 = to_tf32(v0); v1 = to_tf32(v1);
            v2 = to_tf32(v2); v3 = to_tf32(v3);
            *reinterpret_cast<float2*>(A + r0 * ASM + C) = make_float2(v0, v1);
            *reinterpret_cast<float2*>(A + (r0 + 8) * ASM + C) = make_float2(v2, v3);
        }
    }
    __syncthreads();
}

__global__ void __launch_bounds__(256, 2) fused_mlp(
    const float* __restrict__ b0, const float* __restrict__ b1,
    const float* __restrict__ b2, const float* __restrict__ b3,
    const float* __restrict__ bf,
    const float* __restrict__ Wsig, const float* __restrict__ bs,
    const float* __restrict__ Wr,   const float* __restrict__ br,
    float* __restrict__ out)
{
    extern __shared__ float sm[];
    float* A   = sm;                    // 128 x ASM
    float* Wb  = sm + 128 * ASM;        // 2 x 32 x WSM
    float* wsv = Wb + 2 * 32 * WSM;
    float* wrv = wsv + 128;

    int tid = threadIdx.x;
    int lane = tid & 31, wid = tid >> 5;
    int w_r = wid & 3, w_c = wid >> 2;
    int g = lane >> 2, t = lane & 3;
    int rowBlk = blockIdx.x * 128;
    const float* xsrc = g_X + (size_t)rowBlk * 128;

    if (tid < 128) wsv[tid] = Wsig[tid];
    if (tid < 192) wrv[tid] = Wr[tid];

    {
        const float4* src = reinterpret_cast<const float4*>(xsrc);
#pragma unroll
        for (int i = 0; i < 16; i++) {
            int f4 = tid + i * 256;
            float4 v = src[f4];
            int row = f4 >> 5, c4 = f4 & 31;
            *reinterpret_cast<float4*>(A + row * ASM + c4 * 4) = v;
        }
    }
    __syncthreads();

    float acc[2][8][4];
    float sigR = 0.f;

#define CLR() do { _Pragma("unroll") for (int _m = 0; _m < 2; _m++) \
    _Pragma("unroll") for (int _j = 0; _j < 8; _j++) \
    _Pragma("unroll") for (int _i = 0; _i < 4; _i++) acc[_m][_j][_i] = 0.f; } while (0)

    CLR();
    run128_db(g_W0p, acc, A, Wb, tid, w_r, w_c, g, t);
    ep128(acc, b0, true, A, w_r, w_c, g, t);

    CLR();
    run128_db(g_W1p, acc, A, Wb, tid, w_r, w_c, g, t);
    ep128(acc, b1, true, A, w_r, w_c, g, t);

    // L2: skip folded, K=256
    CLR();
    run128_db(g_W2hp, acc, A, Wb, tid, w_r, w_c, g, t);
    run128_sx(g_W2xp, acc, A, Wb, tid, w_r, w_c, g, t, xsrc);
    ep128(acc, b2, true, A, w_r, w_c, g, t);

    CLR();
    run128_db(g_W3p, acc, A, Wb, tid, w_r, w_c, g, t);
    ep128(acc, b3, true, A, w_r, w_c, g, t);

    // sigma = h @ Ws + bs
    if (tid < 128) {
        float s = 0.f;
#pragma unroll
        for (int k4 = 0; k4 < 32; k4++) {
            float4 hv = *reinterpret_cast<const float4*>(A + tid * ASM + k4 * 4);
            s = fmaf(hv.x, wsv[k4 * 4 + 0], s);
            s = fmaf(hv.y, wsv[k4 * 4 + 1], s);
            s = fmaf(hv.z, wsv[k4 * 4 + 2], s);
            s = fmaf(hv.w, wsv[k4 * 4 + 3], s);
        }
        sigR = s + bs[0];
    }

    CLR();
    run128_db(g_Wfp, acc, A, Wb, tid, w_r, w_c, g, t);
    ep128(acc, bf, false, A, w_r, w_c, g, t);

    // dir layer: d = relu(final @ Wdf + V), 64 cols
    CLR();
    {
        int sc4 = (tid & 15) * 4;
        int sk  = (tid >> 4) * 2;
        for (int tt = 0; tt < 4; tt++) {
            __syncthreads();
#pragma unroll
            for (int i = 0; i < 2; i++) {
                float4 v = *reinterpret_cast<const float4*>(
                    g_Wdfp + (size_t)(tt * 32 + sk + i) * 64 + sc4);
                *reinterpret_cast<float4*>(Wb + (sk + i) * WSM + sc4) = v;
            }
            __syncthreads();
#pragma unroll
            for (int k8 = 0; k8 < 4; k8++) {
                int ak = tt * 32 + k8 * 8;
                int r0 = w_r * 32 + g;
                float a0[4], a1[4];
                a0[0] = A[r0 * ASM + ak + t];
                a0[1] = A[(r0 + 8) * ASM + ak + t];
                a0[2] = A[r0 * ASM + ak + t + 4];
                a0[3] = A[(r0 + 8) * ASM + ak + t + 4];
                a1[0] = A[(r0 + 16) * ASM + ak + t];
                a1[1] = A[(r0 + 24) * ASM + ak + t];
                a1[2] = A[(r0 + 16) * ASM + ak + t + 4];
                a1[3] = A[(r0 + 24) * ASM + ak + t + 4];
                int kw = k8 * 8;
#pragma unroll
                for (int j = 0; j < 4; j++) {
                    int cb = w_c * 32 + j * 8 + g;
                    float b0 = Wb[(kw + t) * WSM + cb];
                    float b1 = Wb[(kw + t + 4) * WSM + cb];
                    mma8(acc[0][j], a0, b0, b1);
                    mma8(acc[1][j], a1, b0, b1);
                }
            }
        }
    }
    __syncthreads();
#pragma unroll
    for (int m = 0; m < 2; m++) {
        int r0 = w_r * 32 + m * 16 + g;
#pragma unroll
        for (int j = 0; j < 4; j++) {
            int C = w_c * 32 + j * 8 + 2 * t;
            float2 va = *reinterpret_cast<const float2*>(
                g_V + (size_t)(rowBlk + r0) * 64 + C);
            float2 vb = *reinterpret_cast<const float2*>(
                g_V + (size_t)(rowBlk + r0 + 8) * 64 + C);
            float v0 = fmaxf(acc[m][j][0] + va.x, 0.f);
            float v1 = fmaxf(acc[m][j][1] + va.y, 0.f);
            float v2 = fmaxf(acc[m][j][2] + vb.x, 0.f);
            float v3 = fmaxf(acc[m][j][3] + vb.y, 0.f);
            *reinterpret_cast<float2*>(A + r0 * ASM + C) = make_float2(v0, v1);
            *reinterpret_cast<float2*>(A + (r0 + 8) * ASM + C) = make_float2(v2, v3);
        }
    }
    __syncthreads();

    // rgb + output
    if (tid < 128) {
        float r0 = br[0], r1 = br[1], r2 = br[2];
#pragma unroll
        for (int k4 = 0; k4 < 16; k4++) {
            float4 dv = *reinterpret_cast<const float4*>(A + tid * ASM + k4 * 4);
            const float* wr0 = wrv + k4 * 12;
            r0 = fmaf(dv.x, wr0[0], r0); r1 = fmaf(dv.x, wr0[1], r1); r2 = fmaf(dv.x, wr0[2], r2);
            r0 = fmaf(dv.y, wr0[3], r0); r1 = fmaf(dv.y, wr0[4], r1); r2 = fmaf(dv.y, wr0[5], r2);
            r0 = fmaf(dv.z, wr0[6], r0); r1 = fmaf(dv.z, wr0[7], r1); r2 = fmaf(dv.z, wr0[8], r2);
            r0 = fmaf(dv.w, wr0[9], r0); r1 = fmaf(dv.w, wr0[10], r1); r2 = fmaf(dv.w, wr0[11], r2);
        }
        *reinterpret_cast<float4*>(out + (size_t)(rowBlk + tid) * 4) =
            make_float4(r0, r1, r2, sigR);
    }
}

// ---------------------------------------------------------------------------
extern "C" void kernel_launch(void* const* d_in, const int* in_sizes, int n_in,
                              void* d_out, int out_size) {
    const int*   indices = (const int*)  d_in[0];
    const float* qp      = (const float*)d_in[1];
    const float* xyzdir  = (const float*)d_in[2];
    const float* cpos    = (const float*)d_in[3];
    const float* codes   = (const float*)d_in[4];
    const float* W0 = (const float*)d_in[5],  *b0 = (const float*)d_in[6];
    const float* W1 = (const float*)d_in[7],  *b1 = (const float*)d_in[8];
    const float* W2 = (const float*)d_in[9],  *b2 = (const float*)d_in[10];
    const float* W3 = (const float*)d_in[11], *b3 = (const float*)d_in[12];
    const float* Wf = (const float*)d_in[13], *bf = (const float*)d_in[14];
    const float* Wd = (const float*)d_in[15], *bd = (const float*)d_in[16];
    const float* Ws = (const float*)d_in[17], *bs = (const float*)d_in[18];
    const float* Wr = (const float*)d_in[19], *br = (const float*)d_in[20];
    float* out = (float*)d_out;

    const int smemBytes = SMEM_FLOATS * 4;
    cudaFuncSetAttribute(fused_mlp, cudaFuncAttributeMaxDynamicSharedMemorySize,
                         smemBytes);

    void* histPtr = nullptr;
    cudaGetSymbolAddress(&histPtr, g_hist);
    cudaMemsetAsync(histPtr, 0, 4096 * sizeof(int));

    hist_k<<<NQ / 256, 256>>>(qp);
    sort_codes<<<1, 256>>>(indices, cpos);
    prologue_k<<<5344, 256>>>(W0, W1, W2, W3, Wf, Wd, bd, xyzdir);
    scan_k<<<1, 1024>>>();
    scatter_k<<<NQ / 256, 256>>>(qp);
    knn_interp<<<NQ / 128, 128>>>(indices, qp, codes);
    fused_mlp<<<NQ / 128, 256, smemBytes>>>(b0, b1, b2, b3, bf,
                                            Ws, bs, Wr, br, out);
}

// round 15
// speedup vs baseline: 1.2304x; 1.2304x over previous
#include <cuda_runtime.h>
#include <cstdint>

#define NQ 65536
#define NC 2048
#define ASM 132   // activation smem row stride (floats), 132 % 32 == 4
#define WSM 136   // weight-tile smem row stride (floats), 136 % 32 == 8

// ------- device scratch (static __device__ globals: allocation-free) -------
__device__ float g_X[NQ * 128];    // tf32-rounded [query_codes 64 | xyz 63 | 0]
__device__ float g_V[NQ * 64];     // dir @ Wd_dir + bd  (fp32)
__device__ int   g_hist[4096];
__device__ int   g_offs[4096];
__device__ int   g_perm[NQ];
__device__ float g_W0p[128 * 128]; // all weights tf32-rounded, padded
__device__ float g_W1p[128 * 128];
__device__ float g_W2xp[128 * 128];
__device__ float g_W2hp[128 * 128];
__device__ float g_W3p[128 * 128];
__device__ float g_Wfp[128 * 128];
__device__ float g_Wdfp[128 * 64];

// ------------------------- helpers -----------------------------------------
__device__ __forceinline__ float to_tf32(float x) {
    float r; asm("cvt.rna.tf32.f32 %0, %1;" : "=f"(r) : "f"(x)); return r;
}
__device__ __forceinline__ void mma8(float* c, const float* a, float b0, float b1) {
    asm volatile(
        "mma.sync.aligned.m16n8k8.row.col.f32.tf32.tf32.f32 "
        "{%0,%1,%2,%3}, {%4,%5,%6,%7}, {%8,%9}, {%0,%1,%2,%3};"
        : "+f"(c[0]), "+f"(c[1]), "+f"(c[2]), "+f"(c[3])
        : "r"(__float_as_uint(a[0])), "r"(__float_as_uint(a[1])),
          "r"(__float_as_uint(a[2])), "r"(__float_as_uint(a[3])),
          "r"(__float_as_uint(b0)), "r"(__float_as_uint(b1)));
}
__device__ __forceinline__ int cell_of(float x, float y, float z) {
    int ix = min(15, max(0, (int)(x * 16.f)));
    int iy = min(15, max(0, (int)(y * 16.f)));
    int iz = min(15, max(0, (int)(z * 16.f)));
    return (ix << 8) | (iy << 4) | iz;
}

// --------------------- spatial counting sort of queries --------------------
__global__ void __launch_bounds__(1024) scan_k() {   // 1 block
    __shared__ int s[1024];
    int tid = threadIdx.x;
    int v[4]; int sum = 0;
#pragma unroll
    for (int i = 0; i < 4; i++) { v[i] = g_hist[tid * 4 + i]; sum += v[i]; }
    s[tid] = sum; __syncthreads();
    for (int off = 1; off < 1024; off <<= 1) {
        int t = (tid >= off) ? s[tid - off] : 0;
        __syncthreads();
        s[tid] += t;
        __syncthreads();
    }
    int run = tid ? s[tid - 1] : 0;
#pragma unroll
    for (int i = 0; i < 4; i++) { g_offs[tid * 4 + i] = run; run += v[i]; }
}

__global__ void scatter_k(const float* __restrict__ qp) {
    int q = blockIdx.x * 256 + threadIdx.x;
    int cell = cell_of(qp[3 * q], qp[3 * q + 1], qp[3 * q + 2]);
    int pos = atomicAdd(&g_offs[cell], 1);
    g_perm[pos] = q;
}

// -- merged prologue: weight prep (tf32) | xyz pack | V comp | query hist ---
// blocks [0,224): weights; [224,1248): xyz pack; [1248,5344): V; [5344,5600): hist
__global__ void __launch_bounds__(256) prologue_k(
        const float* __restrict__ W0, const float* __restrict__ W1,
        const float* __restrict__ W2, const float* __restrict__ W3,
        const float* __restrict__ Wf, const float* __restrict__ Wd,
        const float* __restrict__ bd, const float* __restrict__ xyzdir,
        const float* __restrict__ qp) {
    int bid = blockIdx.x;
    int tid = threadIdx.x;
    const int T = 16384;
    if (bid < 224) {
        int total = 6 * T + 8192;
        for (int i = bid * 256 + tid; i < total; i += 224 * 256) {
            if (i < T) {
                int r = i >> 7, c = i & 127;
                g_W0p[i] = (r < 127) ? to_tf32(W0[r * 128 + c]) : 0.f;
            } else if (i < 2 * T) {
                int j = i - T;
                g_W1p[j] = to_tf32(W1[j]);
            } else if (i < 3 * T) {
                int j = i - 2 * T; int r = j >> 7, c = j & 127;
                g_W2xp[j] = (r < 127) ? to_tf32(W2[r * 128 + c]) : 0.f;
            } else if (i < 4 * T) {
                int j = i - 3 * T; int r = j >> 7, c = j & 127;
                g_W2hp[j] = to_tf32(W2[(127 + r) * 128 + c]);
            } else if (i < 5 * T) {
                int j = i - 4 * T;
                g_W3p[j] = to_tf32(W3[j]);
            } else if (i < 6 * T) {
                int j = i - 5 * T;
                g_Wfp[j] = to_tf32(Wf[j]);
            } else {
                int j = i - 6 * T;
                g_Wdfp[j] = to_tf32(Wd[j]);
            }
        }
    } else if (bid < 1248) {
        const int total = NQ * 64;
        for (int i = (bid - 224) * 256 + tid; i < total; i += 1024 * 256) {
            int q = i >> 6, e = i & 63;
            g_X[q * 128 + 64 + e] = (e < 63) ? to_tf32(xyzdir[q * 90 + e]) : 0.f;
        }
    } else if (bid < 5344) {
        __shared__ float sw[27 * 64];
        __shared__ float sb[64];
        for (int i = tid; i < 27 * 64; i += 256) sw[i] = Wd[128 * 64 + i];
        if (tid < 64) sb[tid] = bd[tid];
        __syncthreads();
        int idx = (bid - 1248) * 256 + tid;     // NQ*16 threads
        int q = idx >> 4, c0 = (idx & 15) * 4;
        float a0 = sb[c0], a1 = sb[c0 + 1], a2 = sb[c0 + 2], a3 = sb[c0 + 3];
        const float* dirp = xyzdir + (size_t)q * 90 + 63;
#pragma unroll
        for (int k = 0; k < 27; k++) {
            float dv = dirp[k];
            a0 = fmaf(dv, sw[k * 64 + c0 + 0], a0);
            a1 = fmaf(dv, sw[k * 64 + c0 + 1], a1);
            a2 = fmaf(dv, sw[k * 64 + c0 + 2], a2);
            a3 = fmaf(dv, sw[k * 64 + c0 + 3], a3);
        }
        *reinterpret_cast<float4*>(g_V + (size_t)q * 64 + c0) =
            make_float4(a0, a1, a2, a3);
    } else {
        int q = (bid - 5344) * 256 + tid;
        atomicAdd(&g_hist[cell_of(qp[3 * q], qp[3 * q + 1], qp[3 * q + 2])], 1);
    }
}

// --------- KNN(16) + interpolation, fused; clustered queries ---------------
// Inner loop: 4-wide min pre-check -> one compare/branch per 4 candidates.
__global__ void __launch_bounds__(128) knn_interp(const int* __restrict__ indices,
                                                  const float* __restrict__ qp,
                                                  const float* __restrict__ cpos,
                                                  const float* __restrict__ codes) {
    __shared__ float4 sp[NC];      // {x, y, z, ||c||^2}
    __shared__ float s_w[128 * 16];
    __shared__ int   s_i[128 * 16];
    int tid = threadIdx.x;
    int ib = indices[0];
    const float* cp = cpos + (size_t)ib * NC * 3;
    const float* cc = codes + (size_t)ib * NC * 64;
    for (int c = tid; c < NC; c += 128) {
        float x = cp[c * 3 + 0], y = cp[c * 3 + 1], z = cp[c * 3 + 2];
        sp[c] = make_float4(x, y, z, fmaf(x, x, fmaf(y, y, z * z)));
    }
    __syncthreads();

    int q = g_perm[blockIdx.x * 128 + tid];
    float qx = qp[q * 3 + 0], qy = qp[q * 3 + 1], qz = qp[q * 3 + 2];
    float qx2 = -2.f * qx, qy2 = -2.f * qy, qz2 = -2.f * qz;
    float q2 = fmaf(qx, qx, fmaf(qy, qy, qz * qz));

    unsigned bk[16];
#pragma unroll
    for (int j = 0; j < 16; j++) bk[j] = 0x7F7FFFFFu;
    float bnd = __uint_as_float(0x7F7FF800u) - q2;

    for (int c = 0; c < NC; c += 4) {
        float dp[4];
#pragma unroll
        for (int i = 0; i < 4; i++) {
            float4 v = sp[c + i];
            dp[i] = fmaf(v.x, qx2, fmaf(v.y, qy2, fmaf(v.z, qz2, v.w)));
        }
        float mn4 = fminf(fminf(dp[0], dp[1]), fminf(dp[2], dp[3]));
        if (mn4 < bnd) {
#pragma unroll
            for (int i = 0; i < 4; i++) {
                if (dp[i] < bnd) {
                    float dfull = fmaxf(dp[i] + q2, 0.f);
                    unsigned cur = (__float_as_uint(dfull) & 0xFFFFF800u)
                                 | (unsigned)(c + i);
#pragma unroll
                    for (int j = 0; j < 16; j++) {
                        unsigned lo = min(bk[j], cur);
                        unsigned hi = max(bk[j], cur);
                        bk[j] = lo; cur = hi;
                    }
                    bnd = __uint_as_float(bk[15] & 0xFFFFF800u) - q2;
                }
            }
        }
    }

    float w[16]; int ci[16]; float wsum = 0.f;
#pragma unroll
    for (int k = 0; k < 16; k++) {
        int c = (int)(bk[k] & 0x7FFu); ci[k] = c;
        float4 v = sp[c];
        float dx = qx - v.x, dy = qy - v.y, dz = qz - v.z;
        float d2 = fmaf(dx, dx, fmaf(dy, dy, dz * dz)) + 1e-16f;
        w[k] = 1.0f / d2; wsum += w[k];
    }
    float inv = 1.0f / wsum;
#pragma unroll
    for (int k = 0; k < 16; k++) {
        s_w[tid * 16 + k] = w[k] * inv;
        s_i[tid * 16 + k] = ci[k];
    }
    __syncwarp();

    int lane = tid & 31;
    int wbase2 = tid & ~31;
    for (int s = 0; s < 32; s++) {
        int t = wbase2 + s;
        int qq = __shfl_sync(0xFFFFFFFFu, q, s);
        float a0 = 0.f, a1 = 0.f;
#pragma unroll
        for (int k = 0; k < 16; k++) {
            int cix = s_i[t * 16 + k];
            float wk = s_w[t * 16 + k];
            const float* row = cc + cix * 64;
            a0 = fmaf(wk, row[lane], a0);
            a1 = fmaf(wk, row[lane + 32], a1);
        }
        g_X[(size_t)qq * 128 + lane] = to_tf32(a0);
        g_X[(size_t)qq * 128 + 32 + lane] = to_tf32(a1);
    }
}

// ===================== fused MLP: tf32 mma.sync ============================
// Warp grid 4x2. Warp tile 32x64 (32x32 dir). Double-buffered weight tiles.
#define SMEM_FLOATS (128 * ASM + 2 * 32 * WSM + 128 + 192)

__device__ __forceinline__ void mma_tile(float acc[2][8][4], const float* A,
        const float* Wt, int abase, int w_r, int w_c, int g, int t) {
#pragma unroll
    for (int k8 = 0; k8 < 4; k8++) {
        int ak = abase + k8 * 8;
        int r0 = w_r * 32 + g;
        float a0[4], a1[4];
        a0[0] = A[r0 * ASM + ak + t];
        a0[1] = A[(r0 + 8) * ASM + ak + t];
        a0[2] = A[r0 * ASM + ak + t + 4];
        a0[3] = A[(r0 + 8) * ASM + ak + t + 4];
        a1[0] = A[(r0 + 16) * ASM + ak + t];
        a1[1] = A[(r0 + 24) * ASM + ak + t];
        a1[2] = A[(r0 + 16) * ASM + ak + t + 4];
        a1[3] = A[(r0 + 24) * ASM + ak + t + 4];
        int kw = k8 * 8;
#pragma unroll
        for (int j = 0; j < 8; j++) {
            int cb = w_c * 64 + j * 8 + g;
            float b0 = Wt[(kw + t) * WSM + cb];
            float b1 = Wt[(kw + t + 4) * WSM + cb];
            mma8(acc[0][j], a0, b0, b1);
            mma8(acc[1][j], a1, b0, b1);
        }
    }
}

__device__ __forceinline__ void run128_db(const float* __restrict__ Wg,
        float acc[2][8][4], const float* A, float* Wb,
        int tid, int w_r, int w_c, int g, int t) {
    int sc4 = (tid & 31) * 4;
    int sk  = (tid >> 5) * 4;
    float4 pf[4];
#pragma unroll
    for (int i = 0; i < 4; i++)
        pf[i] = *reinterpret_cast<const float4*>(Wg + (size_t)(sk + i) * 128 + sc4);
#pragma unroll
    for (int i = 0; i < 4; i++)
        *reinterpret_cast<float4*>(Wb + (sk + i) * WSM + sc4) = pf[i];
    __syncthreads();
    for (int tt = 0; tt < 4; tt++) {
        if (tt < 3) {
#pragma unroll
            for (int i = 0; i < 4; i++)
                pf[i] = *reinterpret_cast<const float4*>(
                    Wg + (size_t)((tt + 1) * 32 + sk + i) * 128 + sc4);
        }
        mma_tile(acc, A, Wb + (tt & 1) * (32 * WSM), tt * 32, w_r, w_c, g, t);
        if (tt < 3) {
            float* d = Wb + ((tt + 1) & 1) * (32 * WSM);
#pragma unroll
            for (int i = 0; i < 4; i++)
                *reinterpret_cast<float4*>(d + (sk + i) * WSM + sc4) = pf[i];
        }
        __syncthreads();
    }
}

__device__ __forceinline__ void run128_sx(const float* __restrict__ Wg,
        float acc[2][8][4], float* A, float* Wb,
        int tid, int w_r, int w_c, int g, int t,
        const float* __restrict__ xsrc) {
    int sc4 = (tid & 31) * 4;
    int sk  = (tid >> 5) * 4;
    for (int tt = 0; tt < 4; tt++) {
        __syncthreads();
#pragma unroll
        for (int i = 0; i < 4; i++) {
            float4 v = *reinterpret_cast<const float4*>(
                Wg + (size_t)(tt * 32 + sk + i) * 128 + sc4);
            *reinterpret_cast<float4*>(Wb + (sk + i) * WSM + sc4) = v;
        }
#pragma unroll
        for (int i = 0; i < 4; i++) {
            int row = (tid >> 3) + i * 32;
            int c4 = (tid & 7) * 4;
            float4 v = *reinterpret_cast<const float4*>(
                xsrc + (size_t)row * 128 + tt * 32 + c4);
            *reinterpret_cast<float4*>(A + row * ASM + c4) = v;
        }
        __syncthreads();
        mma_tile(acc, A, Wb, 0, w_r, w_c, g, t);
    }
    __syncthreads();
}

__device__ __forceinline__ void ep128(float acc[2][8][4],
        const float* __restrict__ bias, bool relu,
        float* A, int w_r, int w_c, int g, int t) {
    __syncthreads();
#pragma unroll
    for (int m = 0; m < 2; m++) {
        int r0 = w_r * 32 + m * 16 + g;
#pragma unroll
        for (int j = 0; j < 8; j++) {
            int C = w_c * 64 + j * 8 + 2 * t;
            float bv0 = bias[C], bv1 = bias[C + 1];
            float v0 = acc[m][j][0] + bv0, v1 = acc[m][j][1] + bv1;
            float v2 = acc[m][j][2] + bv0, v3 = acc[m][j][3] + bv1;
            if (relu) {
                v0 = fmaxf(v0, 0.f); v1 = fmaxf(v1, 0.f);
                v2 = fmaxf(v2, 0.f); v3 = fmaxf(v3, 0.f);
            }
            v0 = to_tf32(v0); v1 = to_tf32(v1);
            v2 = to_tf32(v2); v3 = to_tf32(v3);
            *reinterpret_cast<float2*>(A + r0 * ASM + C) = make_float2(v0, v1);
            *reinterpret_cast<float2*>(A + (r0 + 8) * ASM + C) = make_float2(v2, v3);
        }
    }
    __syncthreads();
}

__global__ void __launch_bounds__(256, 2) fused_mlp(
    const float* __restrict__ b0, const float* __restrict__ b1,
    const float* __restrict__ b2, const float* __restrict__ b3,
    const float* __restrict__ bf,
    const float* __restrict__ Wsig, const float* __restrict__ bs,
    const float* __restrict__ Wr,   const float* __restrict__ br,
    float* __restrict__ out)
{
    extern __shared__ float sm[];
    float* A   = sm;                    // 128 x ASM
    float* Wb  = sm + 128 * ASM;        // 2 x 32 x WSM
    float* wsv = Wb + 2 * 32 * WSM;
    float* wrv = wsv + 128;

    int tid = threadIdx.x;
    int lane = tid & 31, wid = tid >> 5;
    int w_r = wid & 3, w_c = wid >> 2;
    int g = lane >> 2, t = lane & 3;
    int rowBlk = blockIdx.x * 128;
    const float* xsrc = g_X + (size_t)rowBlk * 128;

    if (tid < 128) wsv[tid] = Wsig[tid];
    if (tid < 192) wrv[tid] = Wr[tid];

    {
        const float4* src = reinterpret_cast<const float4*>(xsrc);
#pragma unroll
        for (int i = 0; i < 16; i++) {
            int f4 = tid + i * 256;
            float4 v = src[f4];
            int row = f4 >> 5, c4 = f4 & 31;
            *reinterpret_cast<float4*>(A + row * ASM + c4 * 4) = v;
        }
    }
    __syncthreads();

    float acc[2][8][4];
    float sigR = 0.f;

#define CLR() do { _Pragma("unroll") for (int _m = 0; _m < 2; _m++) \
    _Pragma("unroll") for (int _j = 0; _j < 8; _j++) \
    _Pragma("unroll") for (int _i = 0; _i < 4; _i++) acc[_m][_j][_i] = 0.f; } while (0)

    CLR();
    run128_db(g_W0p, acc, A, Wb, tid, w_r, w_c, g, t);
    ep128(acc, b0, true, A, w_r, w_c, g, t);

    CLR();
    run128_db(g_W1p, acc, A, Wb, tid, w_r, w_c, g, t);
    ep128(acc, b1, true, A, w_r, w_c, g, t);

    // L2: skip folded, K=256
    CLR();
    run128_db(g_W2hp, acc, A, Wb, tid, w_r, w_c, g, t);
    run128_sx(g_W2xp, acc, A, Wb, tid, w_r, w_c, g, t, xsrc);
    ep128(acc, b2, true, A, w_r, w_c, g, t);

    CLR();
    run128_db(g_W3p, acc, A, Wb, tid, w_r, w_c, g, t);
    ep128(acc, b3, true, A, w_r, w_c, g, t);

    // sigma = h @ Ws + bs
    if (tid < 128) {
        float s = 0.f;
#pragma unroll
        for (int k4 = 0; k4 < 32; k4++) {
            float4 hv = *reinterpret_cast<const float4*>(A + tid * ASM + k4 * 4);
            s = fmaf(hv.x, wsv[k4 * 4 + 0], s);
            s = fmaf(hv.y, wsv[k4 * 4 + 1], s);
            s = fmaf(hv.z, wsv[k4 * 4 + 2], s);
            s = fmaf(hv.w, wsv[k4 * 4 + 3], s);
        }
        sigR = s + bs[0];
    }

    CLR();
    run128_db(g_Wfp, acc, A, Wb, tid, w_r, w_c, g, t);
    ep128(acc, bf, false, A, w_r, w_c, g, t);

    // dir layer: d = relu(final @ Wdf + V), 64 cols
    CLR();
    {
        int sc4 = (tid & 15) * 4;
        int sk  = (tid >> 4) * 2;
        for (int tt = 0; tt < 4; tt++) {
            __syncthreads();
#pragma unroll
            for (int i = 0; i < 2; i++) {
                float4 v = *reinterpret_cast<const float4*>(
                    g_Wdfp + (size_t)(tt * 32 + sk + i) * 64 + sc4);
                *reinterpret_cast<float4*>(Wb + (sk + i) * WSM + sc4) = v;
            }
            __syncthreads();
#pragma unroll
            for (int k8 = 0; k8 < 4; k8++) {
                int ak = tt * 32 + k8 * 8;
                int r0 = w_r * 32 + g;
                float a0[4], a1[4];
                a0[0] = A[r0 * ASM + ak + t];
                a0[1] = A[(r0 + 8) * ASM + ak + t];
                a0[2] = A[r0 * ASM + ak + t + 4];
                a0[3] = A[(r0 + 8) * ASM + ak + t + 4];
                a1[0] = A[(r0 + 16) * ASM + ak + t];
                a1[1] = A[(r0 + 24) * ASM + ak + t];
                a1[2] = A[(r0 + 16) * ASM + ak + t + 4];
                a1[3] = A[(r0 + 24) * ASM + ak + t + 4];
                int kw = k8 * 8;
#pragma unroll
                for (int j = 0; j < 4; j++) {
                    int cb = w_c * 32 + j * 8 + g;
                    float b0 = Wb[(kw + t) * WSM + cb];
                    float b1 = Wb[(kw + t + 4) * WSM + cb];
                    mma8(acc[0][j], a0, b0, b1);
                    mma8(acc[1][j], a1, b0, b1);
                }
            }
        }
    }
    __syncthreads();
#pragma unroll
    for (int m = 0; m < 2; m++) {
        int r0 = w_r * 32 + m * 16 + g;
#pragma unroll
        for (int j = 0; j < 4; j++) {
            int C = w_c * 32 + j * 8 + 2 * t;
            float2 va = *reinterpret_cast<const float2*>(
                g_V + (size_t)(rowBlk + r0) * 64 + C);
            float2 vb = *reinterpret_cast<const float2*>(
                g_V + (size_t)(rowBlk + r0 + 8) * 64 + C);
            float v0 = fmaxf(acc[m][j][0] + va.x, 0.f);
            float v1 = fmaxf(acc[m][j][1] + va.y, 0.f);
            float v2 = fmaxf(acc[m][j][2] + vb.x, 0.f);
            float v3 = fmaxf(acc[m][j][3] + vb.y, 0.f);
            *reinterpret_cast<float2*>(A + r0 * ASM + C) = make_float2(v0, v1);
            *reinterpret_cast<float2*>(A + (r0 + 8) * ASM + C) = make_float2(v2, v3);
        }
    }
    __syncthreads();

    // rgb + output
    if (tid < 128) {
        float r0 = br[0], r1 = br[1], r2 = br[2];
#pragma unroll
        for (int k4 = 0; k4 < 16; k4++) {
            float4 dv = *reinterpret_cast<const float4*>(A + tid * ASM + k4 * 4);
            const float* wr0 = wrv + k4 * 12;
            r0 = fmaf(dv.x, wr0[0], r0); r1 = fmaf(dv.x, wr0[1], r1); r2 = fmaf(dv.x, wr0[2], r2);
            r0 = fmaf(dv.y, wr0[3], r0); r1 = fmaf(dv.y, wr0[4], r1); r2 = fmaf(dv.y, wr0[5], r2);
            r0 = fmaf(dv.z, wr0[6], r0); r1 = fmaf(dv.z, wr0[7], r1); r2 = fmaf(dv.z, wr0[8], r2);
            r0 = fmaf(dv.w, wr0[9], r0); r1 = fmaf(dv.w, wr0[10], r1); r2 = fmaf(dv.w, wr0[11], r2);
        }
        *reinterpret_cast<float4*>(out + (size_t)(rowBlk + tid) * 4) =
            make_float4(r0, r1, r2, sigR);
    }
}

// ---------------------------------------------------------------------------
extern "C" void kernel_launch(void* const* d_in, const int* in_sizes, int n_in,
                              void* d_out, int out_size) {
    const int*   indices = (const int*)  d_in[0];
    const float* qp      = (const float*)d_in[1];
    const float* xyzdir  = (const float*)d_in[2];
    const float* cpos    = (const float*)d_in[3];
    const float* codes   = (const float*)d_in[4];
    const float* W0 = (const float*)d_in[5],  *b0 = (const float*)d_in[6];
    const float* W1 = (const float*)d_in[7],  *b1 = (const float*)d_in[8];
    const float* W2 = (const float*)d_in[9],  *b2 = (const float*)d_in[10];
    const float* W3 = (const float*)d_in[11], *b3 = (const float*)d_in[12];
    const float* Wf = (const float*)d_in[13], *bf = (const float*)d_in[14];
    const float* Wd = (const float*)d_in[15], *bd = (const float*)d_in[16];
    const float* Ws = (const float*)d_in[17], *bs = (const float*)d_in[18];
    const float* Wr = (const float*)d_in[19], *br = (const float*)d_in[20];
    float* out = (float*)d_out;

    const int smemBytes = SMEM_FLOATS * 4;
    cudaFuncSetAttribute(fused_mlp, cudaFuncAttributeMaxDynamicSharedMemorySize,
                         smemBytes);

    void* histPtr = nullptr;
    cudaGetSymbolAddress(&histPtr, g_hist);
    cudaMemsetAsync(histPtr, 0, 4096 * sizeof(int));

    prologue_k<<<5600, 256>>>(W0, W1, W2, W3, Wf, Wd, bd, xyzdir, qp);
    scan_k<<<1, 1024>>>();
    scatter_k<<<NQ / 256, 256>>>(qp);
    knn_interp<<<NQ / 128, 128>>>(indices, qp, cpos, codes);
    fused_mlp<<<NQ / 128, 256, smemBytes>>>(b0, b1, b2, b3, bf,
                                            Ws, bs, Wr, br, out);
}

// round 16
// speedup vs baseline: 1.3444x; 1.0927x over previous
#include <cuda_runtime.h>
#include <cstdint>

#define NQ 65536
#define NC 2048
#define ASM 132   // activation smem row stride (floats), 132 % 32 == 4
#define WSM 136   // weight-tile smem row stride (floats), 136 % 32 == 8

typedef unsigned long long ull;

// ------- device scratch (static __device__ globals: allocation-free) -------
__device__ float g_X[NQ * 128];    // tf32-rounded [query_codes 64 | xyz 63 | 0]
__device__ float g_DIR[NQ * 32];   // tf32-rounded [dir 27 | 0 x5]
__device__ int   g_hist[4096];
__device__ int   g_offs[4096];
__device__ int   g_perm[NQ];
__device__ float g_W0p[128 * 128]; // all weights tf32-rounded, padded
__device__ float g_W1p[128 * 128];
__device__ float g_W2xp[128 * 128];
__device__ float g_W2hp[128 * 128];
__device__ float g_W3p[128 * 128];
__device__ float g_Wfp[128 * 128];
__device__ float g_Wdfp[128 * 64]; // Wd rows 0..127
__device__ float g_Wddp[32 * 64];  // Wd rows 128..155 (dir), padded to 32

// ------------------------- helpers -----------------------------------------
__device__ __forceinline__ float to_tf32(float x) {
    float r; asm("cvt.rna.tf32.f32 %0, %1;" : "=f"(r) : "f"(x)); return r;
}
__device__ __forceinline__ ull pk2(float lo, float hi) {
    ull r; asm("mov.b64 %0,{%1,%2};" : "=l"(r) : "f"(lo), "f"(hi)); return r;
}
__device__ __forceinline__ void fma2(ull& c, ull a, ull b) {
    asm("fma.rn.f32x2 %0,%1,%2,%0;" : "+l"(c) : "l"(a), "l"(b));
}
__device__ __forceinline__ ull fma2o(ull a, ull b, ull c) {
    ull r; asm("fma.rn.f32x2 %0,%1,%2,%3;" : "=l"(r) : "l"(a), "l"(b), "l"(c));
    return r;
}
__device__ __forceinline__ float2 up2(ull v) {
    float2 r; asm("mov.b64 {%0,%1},%2;" : "=f"(r.x), "=f"(r.y) : "l"(v)); return r;
}
__device__ __forceinline__ void mma8(float* c, const float* a, float b0, float b1) {
    asm volatile(
        "mma.sync.aligned.m16n8k8.row.col.f32.tf32.tf32.f32 "
        "{%0,%1,%2,%3}, {%4,%5,%6,%7}, {%8,%9}, {%0,%1,%2,%3};"
        : "+f"(c[0]), "+f"(c[1]), "+f"(c[2]), "+f"(c[3])
        : "r"(__float_as_uint(a[0])), "r"(__float_as_uint(a[1])),
          "r"(__float_as_uint(a[2])), "r"(__float_as_uint(a[3])),
          "r"(__float_as_uint(b0)), "r"(__float_as_uint(b1)));
}
__device__ __forceinline__ int cell_of(float x, float y, float z) {
    int ix = min(15, max(0, (int)(x * 16.f)));
    int iy = min(15, max(0, (int)(y * 16.f)));
    int iz = min(15, max(0, (int)(z * 16.f)));
    return (ix << 8) | (iy << 4) | iz;
}

// --------------------- spatial counting sort of queries --------------------
__global__ void __launch_bounds__(1024) scan_k() {   // 1 block
    __shared__ int s[1024];
    int tid = threadIdx.x;
    int v[4]; int sum = 0;
#pragma unroll
    for (int i = 0; i < 4; i++) { v[i] = g_hist[tid * 4 + i]; sum += v[i]; }
    s[tid] = sum; __syncthreads();
    for (int off = 1; off < 1024; off <<= 1) {
        int t = (tid >= off) ? s[tid - off] : 0;
        __syncthreads();
        s[tid] += t;
        __syncthreads();
    }
    int run = tid ? s[tid - 1] : 0;
#pragma unroll
    for (int i = 0; i < 4; i++) { g_offs[tid * 4 + i] = run; run += v[i]; }
}

__global__ void scatter_k(const float* __restrict__ qp) {
    int q = blockIdx.x * 256 + threadIdx.x;
    int cell = cell_of(qp[3 * q], qp[3 * q + 1], qp[3 * q + 2]);
    int pos = atomicAdd(&g_offs[cell], 1);
    g_perm[pos] = q;
}

// - merged prologue: weights (tf32) | xyz pack | dir pack | query hist ------
// blocks [0,224): weights; [224,1248): xyz; [1248,1760): dir; [1760,2016): hist
__global__ void __launch_bounds__(256) prologue_k(
        const float* __restrict__ W0, const float* __restrict__ W1,
        const float* __restrict__ W2, const float* __restrict__ W3,
        const float* __restrict__ Wf, const float* __restrict__ Wd,
        const float* __restrict__ xyzdir, const float* __restrict__ qp) {
    int bid = blockIdx.x;
    int tid = threadIdx.x;
    const int T = 16384;
    if (bid < 224) {
        int total = 6 * T + 8192 + 2048;
        for (int i = bid * 256 + tid; i < total; i += 224 * 256) {
            if (i < T) {
                int r = i >> 7, c = i & 127;
                g_W0p[i] = (r < 127) ? to_tf32(W0[r * 128 + c]) : 0.f;
            } else if (i < 2 * T) {
                int j = i - T;
                g_W1p[j] = to_tf32(W1[j]);
            } else if (i < 3 * T) {
                int j = i - 2 * T; int r = j >> 7, c = j & 127;
                g_W2xp[j] = (r < 127) ? to_tf32(W2[r * 128 + c]) : 0.f;
            } else if (i < 4 * T) {
                int j = i - 3 * T; int r = j >> 7, c = j & 127;
                g_W2hp[j] = to_tf32(W2[(127 + r) * 128 + c]);
            } else if (i < 5 * T) {
                int j = i - 4 * T;
                g_W3p[j] = to_tf32(W3[j]);
            } else if (i < 6 * T) {
                int j = i - 5 * T;
                g_Wfp[j] = to_tf32(Wf[j]);
            } else if (i < 6 * T + 8192) {
                int j = i - 6 * T;
                g_Wdfp[j] = to_tf32(Wd[j]);           // rows 0..127
            } else {
                int j = i - 6 * T - 8192;
                int r = j >> 6, c = j & 63;
                g_Wddp[j] = (r < 27) ? to_tf32(Wd[(128 + r) * 64 + c]) : 0.f;
            }
        }
    } else if (bid < 1248) {
        const int total = NQ * 64;
        for (int i = (bid - 224) * 256 + tid; i < total; i += 1024 * 256) {
            int q = i >> 6, e = i & 63;
            g_X[q * 128 + 64 + e] = (e < 63) ? to_tf32(xyzdir[q * 90 + e]) : 0.f;
        }
    } else if (bid < 1760) {
        const int total = NQ * 32;
        for (int i = (bid - 1248) * 256 + tid; i < total; i += 512 * 256) {
            int q = i >> 5, e = i & 31;
            g_DIR[i] = (e < 27) ? to_tf32(xyzdir[q * 90 + 63 + e]) : 0.f;
        }
    } else {
        int q = (bid - 1760) * 256 + tid;
        atomicAdd(&g_hist[cell_of(qp[3 * q], qp[3 * q + 1], qp[3 * q + 2])], 1);
    }
}

// --------- KNN(16) + interpolation; packed f32x2 distances -----------------
// Positions staged as SoA quads per 4-candidate group:
//   sq[4g+0]={x0..x3} sq[4g+1]={y0..y3} sq[4g+2]={z0..z3} sq[4g+3]={w0..w3}
// dp for 4 candidates = 6 FFMA2 (same rounding order as the scalar version,
// so keys are bit-identical).
__global__ void __launch_bounds__(128) knn_interp(const int* __restrict__ indices,
                                                  const float* __restrict__ qp,
                                                  const float* __restrict__ cpos,
                                                  const float* __restrict__ codes) {
    __shared__ float4 sq[NC];      // SoA quads, 32 KB
    __shared__ float s_w[128 * 16];
    __shared__ int   s_i[128 * 16];
    int tid = threadIdx.x;
    int ib = indices[0];
    const float* cp = cpos + (size_t)ib * NC * 3;
    const float* cc = codes + (size_t)ib * NC * 64;
    float* sqf = reinterpret_cast<float*>(sq);
    for (int c = tid; c < NC; c += 128) {
        float x = cp[c * 3 + 0], y = cp[c * 3 + 1], z = cp[c * 3 + 2];
        float w = fmaf(x, x, fmaf(y, y, z * z));
        int base = (c >> 2) * 16, i = c & 3;
        sqf[base + i] = x; sqf[base + 4 + i] = y;
        sqf[base + 8 + i] = z; sqf[base + 12 + i] = w;
    }
    __syncthreads();

    int q = g_perm[blockIdx.x * 128 + tid];
    float qx = qp[q * 3 + 0], qy = qp[q * 3 + 1], qz = qp[q * 3 + 2];
    float qx2 = -2.f * qx, qy2 = -2.f * qy, qz2 = -2.f * qz;
    float q2 = fmaf(qx, qx, fmaf(qy, qy, qz * qz));
    ull qx2p = pk2(qx2, qx2), qy2p = pk2(qy2, qy2), qz2p = pk2(qz2, qz2);

    unsigned bk[16];
#pragma unroll
    for (int j = 0; j < 16; j++) bk[j] = 0x7F7FFFFFu;
    float bnd = __uint_as_float(0x7F7FF800u) - q2;

    const ulonglong2* sqp = reinterpret_cast<const ulonglong2*>(sq);
    for (int gI = 0; gI < NC / 4; gI++) {
        ulonglong2 xp = sqp[4 * gI + 0];
        ulonglong2 yp = sqp[4 * gI + 1];
        ulonglong2 zp = sqp[4 * gI + 2];
        ulonglong2 wp = sqp[4 * gI + 3];
        // dp = fma(x,qx2, fma(y,qy2, fma(z,qz2, w)))  (scalar-order rounding)
        ull t01 = fma2o(zp.x, qz2p, wp.x);
        fma2(t01, yp.x, qy2p);
        fma2(t01, xp.x, qx2p);
        ull t23 = fma2o(zp.y, qz2p, wp.y);
        fma2(t23, yp.y, qy2p);
        fma2(t23, xp.y, qx2p);
        float2 d01 = up2(t01), d23 = up2(t23);
        float mn4 = fminf(fminf(d01.x, d01.y), fminf(d23.x, d23.y));
        if (mn4 < bnd) {
            float dp[4] = { d01.x, d01.y, d23.x, d23.y };
            int c = gI * 4;
#pragma unroll
            for (int i = 0; i < 4; i++) {
                if (dp[i] < bnd) {
                    float dfull = fmaxf(dp[i] + q2, 0.f);
                    unsigned cur = (__float_as_uint(dfull) & 0xFFFFF800u)
                                 | (unsigned)(c + i);
#pragma unroll
                    for (int j = 0; j < 16; j++) {
                        unsigned lo = min(bk[j], cur);
                        unsigned hi = max(bk[j], cur);
                        bk[j] = lo; cur = hi;
                    }
                    bnd = __uint_as_float(bk[15] & 0xFFFFF800u) - q2;
                }
            }
        }
    }

    float w[16]; int ci[16]; float wsum = 0.f;
#pragma unroll
    for (int k = 0; k < 16; k++) {
        int c = (int)(bk[k] & 0x7FFu); ci[k] = c;
        int base = (c >> 2) * 16, ii = c & 3;
        float dx = qx - sqf[base + ii];
        float dy = qy - sqf[base + 4 + ii];
        float dz = qz - sqf[base + 8 + ii];
        float d2 = fmaf(dx, dx, fmaf(dy, dy, dz * dz)) + 1e-16f;
        w[k] = 1.0f / d2; wsum += w[k];
    }
    float inv = 1.0f / wsum;
#pragma unroll
    for (int k = 0; k < 16; k++) {
        s_w[tid * 16 + k] = w[k] * inv;
        s_i[tid * 16 + k] = ci[k];
    }
    __syncwarp();

    int lane = tid & 31;
    int wbase2 = tid & ~31;
    for (int s = 0; s < 32; s++) {
        int t = wbase2 + s;
        int qq = __shfl_sync(0xFFFFFFFFu, q, s);
        float a0 = 0.f, a1 = 0.f;
#pragma unroll
        for (int k = 0; k < 16; k++) {
            int cix = s_i[t * 16 + k];
            float wk = s_w[t * 16 + k];
            const float* row = cc + cix * 64;
            a0 = fmaf(wk, row[lane], a0);
            a1 = fmaf(wk, row[lane + 32], a1);
        }
        g_X[(size_t)qq * 128 + lane] = to_tf32(a0);
        g_X[(size_t)qq * 128 + 32 + lane] = to_tf32(a1);
    }
}

// ===================== fused MLP: tf32 mma.sync ============================
// Warp grid 4x2. Warp tile 32x64 (32x32 dir). Double-buffered weight tiles.
#define SMEM_FLOATS (128 * ASM + 2 * 32 * WSM + 128 + 192)

__device__ __forceinline__ void mma_tile(float acc[2][8][4], const float* A,
        const float* Wt, int abase, int w_r, int w_c, int g, int t) {
#pragma unroll
    for (int k8 = 0; k8 < 4; k8++) {
        int ak = abase + k8 * 8;
        int r0 = w_r * 32 + g;
        float a0[4], a1[4];
        a0[0] = A[r0 * ASM + ak + t];
        a0[1] = A[(r0 + 8) * ASM + ak + t];
        a0[2] = A[r0 * ASM + ak + t + 4];
        a0[3] = A[(r0 + 8) * ASM + ak + t + 4];
        a1[0] = A[(r0 + 16) * ASM + ak + t];
        a1[1] = A[(r0 + 24) * ASM + ak + t];
        a1[2] = A[(r0 + 16) * ASM + ak + t + 4];
        a1[3] = A[(r0 + 24) * ASM + ak + t + 4];
        int kw = k8 * 8;
#pragma unroll
        for (int j = 0; j < 8; j++) {
            int cb = w_c * 64 + j * 8 + g;
            float b0 = Wt[(kw + t) * WSM + cb];
            float b1 = Wt[(kw + t + 4) * WSM + cb];
            mma8(acc[0][j], a0, b0, b1);
            mma8(acc[1][j], a1, b0, b1);
        }
    }
}

__device__ __forceinline__ void run128_db(const float* __restrict__ Wg,
        float acc[2][8][4], const float* A, float* Wb,
        int tid, int w_r, int w_c, int g, int t) {
    int sc4 = (tid & 31) * 4;
    int sk  = (tid >> 5) * 4;
    float4 pf[4];
#pragma unroll
    for (int i = 0; i < 4; i++)
        pf[i] = *reinterpret_cast<const float4*>(Wg + (size_t)(sk + i) * 128 + sc4);
#pragma unroll
    for (int i = 0; i < 4; i++)
        *reinterpret_cast<float4*>(Wb + (sk + i) * WSM + sc4) = pf[i];
    __syncthreads();
    for (int tt = 0; tt < 4; tt++) {
        if (tt < 3) {
#pragma unroll
            for (int i = 0; i < 4; i++)
                pf[i] = *reinterpret_cast<const float4*>(
                    Wg + (size_t)((tt + 1) * 32 + sk + i) * 128 + sc4);
        }
        mma_tile(acc, A, Wb + (tt & 1) * (32 * WSM), tt * 32, w_r, w_c, g, t);
        if (tt < 3) {
            float* d = Wb + ((tt + 1) & 1) * (32 * WSM);
#pragma unroll
            for (int i = 0; i < 4; i++)
                *reinterpret_cast<float4*>(d + (sk + i) * WSM + sc4) = pf[i];
        }
        __syncthreads();
    }
}

__device__ __forceinline__ void run128_sx(const float* __restrict__ Wg,
        float acc[2][8][4], float* A, float* Wb,
        int tid, int w_r, int w_c, int g, int t,
        const float* __restrict__ xsrc) {
    int sc4 = (tid & 31) * 4;
    int sk  = (tid >> 5) * 4;
    for (int tt = 0; tt < 4; tt++) {
        __syncthreads();
#pragma unroll
        for (int i = 0; i < 4; i++) {
            float4 v = *reinterpret_cast<const float4*>(
                Wg + (size_t)(tt * 32 + sk + i) * 128 + sc4);
            *reinterpret_cast<float4*>(Wb + (sk + i) * WSM + sc4) = v;
        }
#pragma unroll
        for (int i = 0; i < 4; i++) {
            int row = (tid >> 3) + i * 32;
            int c4 = (tid & 7) * 4;
            float4 v = *reinterpret_cast<const float4*>(
                xsrc + (size_t)row * 128 + tt * 32 + c4);
            *reinterpret_cast<float4*>(A + row * ASM + c4) = v;
        }
        __syncthreads();
        mma_tile(acc, A, Wb, 0, w_r, w_c, g, t);
    }
    __syncthreads();
}

__device__ __forceinline__ void ep128(float acc[2][8][4],
        const float* __restrict__ bias, bool relu,
        float* A, int w_r, int w_c, int g, int t) {
    __syncthreads();
#pragma unroll
    for (int m = 0; m < 2; m++) {
        int r0 = w_r * 32 + m * 16 + g;
#pragma unroll
        for (int j = 0; j < 8; j++) {
            int C = w_c * 64 + j * 8 + 2 * t;
            float bv0 = bias[C], bv1 = bias[C + 1];
            float v0 = acc[m][j][0] + bv0, v1 = acc[m][j][1] + bv1;
            float v2 = acc[m][j][2] + bv0, v3 = acc[m][j][3] + bv1;
            if (relu) {
                v0 = fmaxf(v0, 0.f); v1 = fmaxf(v1, 0.f);
                v2 = fmaxf(v2, 0.f); v3 = fmaxf(v3, 0.f);
            }
            v0 = to_tf32(v0); v1 = to_tf32(v1);
            v2 = to_tf32(v2); v3 = to_tf32(v3);
            *reinterpret_cast<float2*>(A + r0 * ASM + C) = make_float2(v0, v1);
            *reinterpret_cast<float2*>(A + (r0 + 8) * ASM + C) = make_float2(v2, v3);
        }
    }
    __syncthreads();
}

__global__ void __launch_bounds__(256, 2) fused_mlp(
    const float* __restrict__ b0, const float* __restrict__ b1,
    const float* __restrict__ b2, const float* __restrict__ b3,
    const float* __restrict__ bf, const float* __restrict__ bd,
    const float* __restrict__ Wsig, const float* __restrict__ bs,
    const float* __restrict__ Wr,   const float* __restrict__ br,
    float* __restrict__ out)
{
    extern __shared__ float sm[];
    float* A   = sm;                    // 128 x ASM
    float* Wb  = sm + 128 * ASM;        // 2 x 32 x WSM
    float* wsv = Wb + 2 * 32 * WSM;
    float* wrv = wsv + 128;

    int tid = threadIdx.x;
    int lane = tid & 31, wid = tid >> 5;
    int w_r = wid & 3, w_c = wid >> 2;
    int g = lane >> 2, t = lane & 3;
    int rowBlk = blockIdx.x * 128;
    const float* xsrc = g_X + (size_t)rowBlk * 128;

    if (tid < 128) wsv[tid] = Wsig[tid];
    if (tid < 192) wrv[tid] = Wr[tid];

    {
        const float4* src = reinterpret_cast<const float4*>(xsrc);
#pragma unroll
        for (int i = 0; i < 16; i++) {
            int f4 = tid + i * 256;
            float4 v = src[f4];
            int row = f4 >> 5, c4 = f4 & 31;
            *reinterpret_cast<float4*>(A + row * ASM + c4 * 4) = v;
        }
    }
    __syncthreads();

    float acc[2][8][4];
    float sigR = 0.f;

#define CLR() do { _Pragma("unroll") for (int _m = 0; _m < 2; _m++) \
    _Pragma("unroll") for (int _j = 0; _j < 8; _j++) \
    _Pragma("unroll") for (int _i = 0; _i < 4; _i++) acc[_m][_j][_i] = 0.f; } while (0)

    CLR();
    run128_db(g_W0p, acc, A, Wb, tid, w_r, w_c, g, t);
    ep128(acc, b0, true, A, w_r, w_c, g, t);

    CLR();
    run128_db(g_W1p, acc, A, Wb, tid, w_r, w_c, g, t);
    ep128(acc, b1, true, A, w_r, w_c, g, t);

    // L2: skip folded, K=256
    CLR();
    run128_db(g_W2hp, acc, A, Wb, tid, w_r, w_c, g, t);
    run128_sx(g_W2xp, acc, A, Wb, tid, w_r, w_c, g, t, xsrc);
    ep128(acc, b2, true, A, w_r, w_c, g, t);

    CLR();
    run128_db(g_W3p, acc, A, Wb, tid, w_r, w_c, g, t);
    ep128(acc, b3, true, A, w_r, w_c, g, t);

    // sigma = h @ Ws + bs
    if (tid < 128) {
        float s = 0.f;
#pragma unroll
        for (int k4 = 0; k4 < 32; k4++) {
            float4 hv = *reinterpret_cast<const float4*>(A + tid * ASM + k4 * 4);
            s = fmaf(hv.x, wsv[k4 * 4 + 0], s);
            s = fmaf(hv.y, wsv[k4 * 4 + 1], s);
            s = fmaf(hv.z, wsv[k4 * 4 + 2], s);
            s = fmaf(hv.w, wsv[k4 * 4 + 3], s);
        }
        sigR = s + bs[0];
    }

    CLR();
    run128_db(g_Wfp, acc, A, Wb, tid, w_r, w_c, g, t);
    ep128(acc, bf, false, A, w_r, w_c, g, t);

    // dir layer: d = relu([final | dir] @ Wd + bd), 64 cols, K=128+32
    CLR();
    {
        int sc4 = (tid & 15) * 4;
        int sk  = (tid >> 4) * 2;
        for (int tt = 0; tt < 4; tt++) {
            __syncthreads();
#pragma unroll
            for (int i = 0; i < 2; i++) {
                float4 v = *reinterpret_cast<const float4*>(
                    g_Wdfp + (size_t)(tt * 32 + sk + i) * 64 + sc4);
                *reinterpret_cast<float4*>(Wb + (sk + i) * WSM + sc4) = v;
            }
            __syncthreads();
#pragma unroll
            for (int k8 = 0; k8 < 4; k8++) {
                int ak = tt * 32 + k8 * 8;
                int r0 = w_r * 32 + g;
                float a0[4], a1[4];
                a0[0] = A[r0 * ASM + ak + t];
                a0[1] = A[(r0 + 8) * ASM + ak + t];
                a0[2] = A[r0 * ASM + ak + t + 4];
                a0[3] = A[(r0 + 8) * ASM + ak + t + 4];
                a1[0] = A[(r0 + 16) * ASM + ak + t];
                a1[1] = A[(r0 + 24) * ASM + ak + t];
                a1[2] = A[(r0 + 16) * ASM + ak + t + 4];
                a1[3] = A[(r0 + 24) * ASM + ak + t + 4];
                int kw = k8 * 8;
#pragma unroll
                for (int j = 0; j < 4; j++) {
                    int cb = w_c * 32 + j * 8 + g;
                    float b0 = Wb[(kw + t) * WSM + cb];
                    float b1 = Wb[(kw + t + 4) * WSM + cb];
                    mma8(acc[0][j], a0, b0, b1);
                    mma8(acc[1][j], a1, b0, b1);
                }
            }
        }
        // extra K=32 tile: dir embedding (staged into A[:,0:32])
        __syncthreads();
#pragma unroll
        for (int i = 0; i < 2; i++) {
            float4 v = *reinterpret_cast<const float4*>(
                g_Wddp + (size_t)(sk + i) * 64 + sc4);
            *reinterpret_cast<float4*>(Wb + (sk + i) * WSM + sc4) = v;
        }
        {
            const float4* dsrc = reinterpret_cast<const float4*>(
                g_DIR + (size_t)rowBlk * 32);
#pragma unroll
            for (int i = 0; i < 4; i++) {
                int f4 = tid + i * 256;
                float4 v = dsrc[f4];
                int row = f4 >> 3, c4 = f4 & 7;
                *reinterpret_cast<float4*>(A + row * ASM + c4 * 4) = v;
            }
        }
        __syncthreads();
#pragma unroll
        for (int k8 = 0; k8 < 4; k8++) {
            int ak = k8 * 8;
            int r0 = w_r * 32 + g;
            float a0[4], a1[4];
            a0[0] = A[r0 * ASM + ak + t];
            a0[1] = A[(r0 + 8) * ASM + ak + t];
            a0[2] = A[r0 * ASM + ak + t + 4];
            a0[3] = A[(r0 + 8) * ASM + ak + t + 4];
            a1[0] = A[(r0 + 16) * ASM + ak + t];
            a1[1] = A[(r0 + 24) * ASM + ak + t];
            a1[2] = A[(r0 + 16) * ASM + ak + t + 4];
            a1[3] = A[(r0 + 24) * ASM + ak + t + 4];
            int kw = k8 * 8;
#pragma unroll
            for (int j = 0; j < 4; j++) {
                int cb = w_c * 32 + j * 8 + g;
                float b0 = Wb[(kw + t) * WSM + cb];
                float b1 = Wb[(kw + t + 4) * WSM + cb];
                mma8(acc[0][j], a0, b0, b1);
                mma8(acc[1][j], a1, b0, b1);
            }
        }
    }
    __syncthreads();
#pragma unroll
    for (int m = 0; m < 2; m++) {
        int r0 = w_r * 32 + m * 16 + g;
#pragma unroll
        for (int j = 0; j < 4; j++) {
            int C = w_c * 32 + j * 8 + 2 * t;
            float bv0 = bd[C], bv1 = bd[C + 1];
            float v0 = fmaxf(acc[m][j][0] + bv0, 0.f);
            float v1 = fmaxf(acc[m][j][1] + bv1, 0.f);
            float v2 = fmaxf(acc[m][j][2] + bv0, 0.f);
            float v3 = fmaxf(acc[m][j][3] + bv1, 0.f);
            *reinterpret_cast<float2*>(A + r0 * ASM + C) = make_float2(v0, v1);
            *reinterpret_cast<float2*>(A + (r0 + 8) * ASM + C) = make_float2(v2, v3);
        }
    }
    __syncthreads();

    // rgb + output
    if (tid < 128) {
        float r0 = br[0], r1 = br[1], r2 = br[2];
#pragma unroll
        for (int k4 = 0; k4 < 16; k4++) {
            float4 dv = *reinterpret_cast<const float4*>(A + tid * ASM + k4 * 4);
            const float* wr0 = wrv + k4 * 12;
            r0 = fmaf(dv.x, wr0[0], r0); r1 = fmaf(dv.x, wr0[1], r1); r2 = fmaf(dv.x, wr0[2], r2);
            r0 = fmaf(dv.y, wr0[3], r0); r1 = fmaf(dv.y, wr0[4], r1); r2 = fmaf(dv.y, wr0[5], r2);
            r0 = fmaf(dv.z, wr0[6], r0); r1 = fmaf(dv.z, wr0[7], r1); r2 = fmaf(dv.z, wr0[8], r2);
            r0 = fmaf(dv.w, wr0[9], r0); r1 = fmaf(dv.w, wr0[10], r1); r2 = fmaf(dv.w, wr0[11], r2);
        }
        *reinterpret_cast<float4*>(out + (size_t)(rowBlk + tid) * 4) =
            make_float4(r0, r1, r2, sigR);
    }
}

// ---------------------------------------------------------------------------
extern "C" void kernel_launch(void* const* d_in, const int* in_sizes, int n_in,
                              void* d_out, int out_size) {
    const int*   indices = (const int*)  d_in[0];
    const float* qp      = (const float*)d_in[1];
    const float* xyzdir  = (const float*)d_in[2];
    const float* cpos    = (const float*)d_in[3];
    const float* codes   = (const float*)d_in[4];
    const float* W0 = (const float*)d_in[5],  *b0 = (const float*)d_in[6];
    const float* W1 = (const float*)d_in[7],  *b1 = (const float*)d_in[8];
    const float* W2 = (const float*)d_in[9],  *b2 = (const float*)d_in[10];
    const float* W3 = (const float*)d_in[11], *b3 = (const float*)d_in[12];
    const float* Wf = (const float*)d_in[13], *bf = (const float*)d_in[14];
    const float* Wd = (const float*)d_in[15], *bd = (const float*)d_in[16];
    const float* Ws = (const float*)d_in[17], *bs = (const float*)d_in[18];
    const float* Wr = (const float*)d_in[19], *br = (const float*)d_in[20];
    float* out = (float*)d_out;

    const int smemBytes = SMEM_FLOATS * 4;
    cudaFuncSetAttribute(fused_mlp, cudaFuncAttributeMaxDynamicSharedMemorySize,
                         smemBytes);

    void* histPtr = nullptr;
    cudaGetSymbolAddress(&histPtr, g_hist);
    cudaMemsetAsync(histPtr, 0, 4096 * sizeof(int));

    prologue_k<<<2016, 256>>>(W0, W1, W2, W3, Wf, Wd, xyzdir, qp);
    scan_k<<<1, 1024>>>();
    scatter_k<<<NQ / 256, 256>>>(qp);
    knn_interp<<<NQ / 128, 128>>>(indices, qp, cpos, codes);
    fused_mlp<<<NQ / 128, 256, smemBytes>>>(b0, b1, b2, b3, bf, bd,
                                            Ws, bs, Wr, br, out);
}